// round 12
// baseline (speedup 1.0000x reference)
#include <cuda_runtime.h>
#include <stdint.h>

#define NN 100000
#define NE 1000000
#define KD 128
#define OD 64

// Scratch: h = X @ W, 100000 x 64 fp32 = 25.6 MB (fits in L2 for the SpMM gather)
__device__ __align__(16) float g_h[(size_t)NN * OD];
__device__ int g_is64;

// Detect whether edge index arrays are int64 or int32.
// For int64 data with values in [0, 2^31), every odd 32-bit word is 0.
__global__ void detect_kernel(const unsigned* __restrict__ er,
                              const unsigned* __restrict__ ec) {
    if (threadIdx.x == 0 && blockIdx.x == 0) {
        int all_zero = 1;
        #pragma unroll 1
        for (int i = 0; i < 64; i++) {
            all_zero &= (er[2 * i + 1] == 0u);
            all_zero &= (ec[2 * i + 1] == 0u);
        }
        g_is64 = all_zero;
    }
}

// Packed f32x2 FMA (Blackwell FFMA2) — only reachable via explicit PTX.
__device__ __forceinline__ void fma2(unsigned long long& acc,
                                     unsigned long long x2,
                                     unsigned long long w2) {
    asm("fma.rn.f32x2 %0, %1, %2, %0;" : "+l"(acc) : "l"(x2), "l"(w2));
}

__device__ __forceinline__ unsigned long long bcast2(float x) {
    unsigned long long r;
    asm("mov.b64 %0, {%1, %1};" : "=l"(r) : "f"(x));
    return r;
}

// h = X @ W. One thread per output row, 64 outputs held as 32 packed f32x2
// accumulators. W (32KB) in smem as packed pairs, broadcast LDS.128.
__global__ __launch_bounds__(256) void gemm_kernel(const float* __restrict__ X,
                                                   const float* __restrict__ W) {
    // Ws[k][c2]: per k-row, 16 ulonglong2 = 32 f32x2 = 64 floats (natural layout)
    __shared__ ulonglong2 Ws[KD * 16];  // 32 KB
    const ulonglong2* W4 = reinterpret_cast<const ulonglong2*>(W);
    for (int i = threadIdx.x; i < KD * 16; i += 256) Ws[i] = W4[i];
    __syncthreads();

    int row = blockIdx.x * 256 + threadIdx.x;
    if (row >= NN) return;

    const float4* xp = reinterpret_cast<const float4*>(X) + (size_t)row * (KD / 4);

    unsigned long long acc[32];
    #pragma unroll
    for (int c = 0; c < 32; c++) acc[c] = 0ull;

    #pragma unroll 1
    for (int k4 = 0; k4 < KD / 4; k4++) {
        float4 xv = __ldg(xp + k4);
        unsigned long long xs[4];
        xs[0] = bcast2(xv.x);
        xs[1] = bcast2(xv.y);
        xs[2] = bcast2(xv.z);
        xs[3] = bcast2(xv.w);
        #pragma unroll
        for (int s = 0; s < 4; s++) {
            const ulonglong2* wr = &Ws[(k4 * 4 + s) * 16];
            #pragma unroll
            for (int c = 0; c < 16; c++) {
                ulonglong2 w = wr[c];
                fma2(acc[2 * c + 0], xs[s], w.x);
                fma2(acc[2 * c + 1], xs[s], w.y);
            }
        }
    }

    ulonglong2* hp = reinterpret_cast<ulonglong2*>(g_h) + (size_t)row * 16;
    #pragma unroll
    for (int c = 0; c < 16; c++) {
        ulonglong2 v;
        v.x = acc[2 * c + 0];
        v.y = acc[2 * c + 1];
        hp[c] = v;
    }
}

// SpMM scatter: 16 threads per edge, one float4 (16B) each.
// red.global.add.v4.f32: 16M no-return vector REDs instead of 64M scalar.
__global__ __launch_bounds__(256) void spmm_kernel(const void* __restrict__ er_raw,
                                                   const void* __restrict__ ec_raw,
                                                   const float* __restrict__ ev,
                                                   float* __restrict__ out) {
    long long t = (long long)blockIdx.x * blockDim.x + threadIdx.x;
    long long e = t >> 4;
    int j = (int)(t & 15);
    if (e >= NE) return;

    long long r, c;
    if (g_is64) {
        r = ((const long long*)er_raw)[e];
        c = ((const long long*)ec_raw)[e];
    } else {
        r = (long long)((const int*)er_raw)[e];
        c = (long long)((const int*)ec_raw)[e];
    }
    float v = __ldg(ev + e);

    const float4* hp = reinterpret_cast<const float4*>(g_h) + c * 16 + j;
    float4 hv = __ldg(hp);

    float4* op = reinterpret_cast<float4*>(out) + r * 16 + j;
    asm volatile("red.global.add.v4.f32 [%0], {%1, %2, %3, %4};"
                 :: "l"(op), "f"(v * hv.x), "f"(v * hv.y),
                    "f"(v * hv.z), "f"(v * hv.w)
                 : "memory");
}

__global__ __launch_bounds__(256) void bias_relu_kernel(const float* __restrict__ bias,
                                                        float* __restrict__ out) {
    int i = blockIdx.x * blockDim.x + threadIdx.x;
    if (i >= NN * (OD / 4)) return;
    float4 b = reinterpret_cast<const float4*>(bias)[i & (OD / 4 - 1)];
    float4* op = reinterpret_cast<float4*>(out) + i;
    float4 o = *op;
    o.x = fmaxf(o.x + b.x, 0.f);
    o.y = fmaxf(o.y + b.y, 0.f);
    o.z = fmaxf(o.z + b.z, 0.f);
    o.w = fmaxf(o.w + b.w, 0.f);
    *op = o;
}

extern "C" void kernel_launch(void* const* d_in, const int* in_sizes, int n_in,
                              void* d_out, int out_size) {
    const float* X    = (const float*)d_in[0];
    const void*  er   = d_in[1];
    const void*  ec   = d_in[2];
    const float* ev   = (const float*)d_in[3];
    const float* W    = (const float*)d_in[4];
    const float* bias = (const float*)d_in[5];
    float* out = (float*)d_out;

    cudaMemsetAsync(d_out, 0, (size_t)NN * OD * sizeof(float), 0);

    detect_kernel<<<1, 32>>>((const unsigned*)er, (const unsigned*)ec);

    gemm_kernel<<<(NN + 255) / 256, 256>>>(X, W);

    long long spmm_threads = (long long)NE * 16;
    spmm_kernel<<<(unsigned)((spmm_threads + 255) / 256), 256>>>(er, ec, ev, out);

    bias_relu_kernel<<<(NN * (OD / 4) + 255) / 256, 256>>>(bias, out);
}